// round 11
// baseline (speedup 1.0000x reference)
#include <cuda_runtime.h>
#include <cuda_fp16.h>
#include <cstdint>

// B=8, N=C=2048, heads=8 -> scale = 1/16.
#define NB 8
#define NN 2048
#define NN2 (2048*2048)
#define SCALE 0.0625f

// ---------------- scratch ----------------------------------------------------
__device__ __align__(256) __half g_xh[(size_t)NB * NN2];   // x as fp16
__device__ __align__(256) __half g_G[(size_t)NB * NN2];    // G = x x^T fp16 (full, symmetric)
__device__ __align__(256) __half g_wq[NN2];                // Wq as fp16
__device__ float        g_v[NB * NN];                      // column means of x
__device__ unsigned int g_m[NB * NN];                      // rowmax of attn (ordered uint)

__device__ __forceinline__ unsigned int float_ord(float f) {
    unsigned int u = __float_as_uint(f);
    return (u & 0x80000000u) ? ~u : (u | 0x80000000u);
}
__device__ __forceinline__ float ord_float(unsigned int o) {
    unsigned int u = (o & 0x80000000u) ? (o ^ 0x80000000u) : ~o;
    return __uint_as_float(u);
}

// ---- small kernels ----------------------------------------------------------
// Wq -> fp16, plus folded init of g_v / g_m.
__global__ void convert_wq(const float* __restrict__ Wq) {
    size_t g = (size_t)blockIdx.x * 256 + threadIdx.x;
    float4 f = ((const float4*)Wq)[g];
    ((__half2*)g_wq)[g * 2]     = __floats2half2_rn(f.x, f.y);
    ((__half2*)g_wq)[g * 2 + 1] = __floats2half2_rn(f.z, f.w);
    if (g < NB * NN) { g_v[g] = 0.0f; g_m[g] = 0u; }
}

// Fused x -> fp16 conversion + column-mean accumulation.
__global__ void convert_x_mean(const float* __restrict__ x) {
    int b = blockIdx.x;
    int c = blockIdx.y * 256 + threadIdx.x;
    int n0 = blockIdx.z * 256;
    const float* xp = x + ((size_t)b * NN + n0) * NN + c;
    __half* hp = g_xh + ((size_t)b * NN + n0) * NN + c;
    float s = 0.0f;
    #pragma unroll 8
    for (int n = 0; n < 256; n++) {
        float f = xp[(size_t)n * NN];
        hp[(size_t)n * NN] = __float2half_rn(f);
        s += f;
    }
    atomicAdd(&g_v[b * NN + c], s * (1.0f / (float)NN));
}

// ---------------- HMMA GEMM (mma.sync m16n8k16 fp16, fp32 accum) -------------
// BKT=64: 32 k-tiles, one barrier per tile, 4 unrolled k-steps (64 MMAs) each.
#define BM 128
#define BN 128
#define BKT 64
#define PADK 72                         // fp16 per smem row (64 data + 8 pad); 144B stride
#define A_BYTES (BM * PADK * 2)         // 18432
#define STG_BYTES (2 * A_BYTES)         // 36864
#define NSTG 3
#define SMEM_BYTES (NSTG * STG_BYTES)   // 110592; 2 CTAs = 221184 <= 228KB/SM
#define NT 32                           // 32 k-tiles of 64 = K 2048
#define TFS 130                         // epi transpose buffer row stride (even)

#define NMT 16
#define NUT 136

__device__ __forceinline__ void ldsm4(uint32_t& d0, uint32_t& d1, uint32_t& d2,
                                      uint32_t& d3, uint32_t addr) {
    asm volatile("ldmatrix.sync.aligned.m8n8.x4.shared.b16 {%0,%1,%2,%3}, [%4];"
                 : "=r"(d0), "=r"(d1), "=r"(d2), "=r"(d3) : "r"(addr));
}
__device__ __forceinline__ void mma16816(float* c, const uint32_t* a, const uint32_t* b) {
    asm volatile(
        "mma.sync.aligned.m16n8k16.row.col.f32.f16.f16.f32 "
        "{%0,%1,%2,%3}, {%4,%5,%6,%7}, {%8,%9}, {%0,%1,%2,%3};"
        : "+f"(c[0]), "+f"(c[1]), "+f"(c[2]), "+f"(c[3])
        : "r"(a[0]), "r"(a[1]), "r"(a[2]), "r"(a[3]), "r"(b[0]), "r"(b[1]));
}
__device__ __forceinline__ void cp16(uint32_t dst, const void* src) {
    asm volatile("cp.async.cg.shared.global [%0], [%1], 16;" :: "r"(dst), "l"(src));
}

// MODE 0: symmetric GEMM (G = A A^T, upper tiles, direct + mirrored fp16 store)
// MODE 1: GEMM A*B^T with fused rowmax over N axis into g_m
template<int MODE>
__global__ __launch_bounds__(256, 2) void hgemm(
    const __half* __restrict__ A, size_t aStride,
    const __half* __restrict__ B, size_t bStride,
    __half* __restrict__ C)
{
    extern __shared__ __align__(16) char smem[];
    const int tid  = threadIdx.x;
    const int lane = tid & 31;
    const int w    = tid >> 5;
    const int wm   = w >> 1;
    const int wn   = w & 1;
    const int b    = blockIdx.z;

    int by, bx;
    if (MODE == 0) {                 // decode upper-tri linear index
        int t = blockIdx.x, i = 0;
        while (t >= NMT - i) { t -= NMT - i; i++; }
        by = i; bx = i + t;
    } else {
        by = blockIdx.y; bx = blockIdx.x;
    }
    const int rowA = by * BM;
    const int rowB = bx * BN;

    const __half* Ab = A + (size_t)b * aStride;
    const __half* Bb = B + (size_t)b * bStride;

    const uint32_t sbase = (uint32_t)__cvta_generic_to_shared(smem);

    auto load_stage = [&](int tile) {
        uint32_t sb = sbase + (tile % NSTG) * STG_BYTES;
        const int kk = tile * BKT;
        // 1024 16B-chunks per matrix (128 rows x 8 chunks); 4 per thread per matrix
        #pragma unroll
        for (int j = 0; j < 4; j++) {
            int qq = tid * 4 + j;
            int r = qq >> 3, c = qq & 7;
            cp16(sb + r * 144 + c * 16, Ab + (size_t)(rowA + r) * NN + kk + c * 8);
            cp16(sb + A_BYTES + r * 144 + c * 16, Bb + (size_t)(rowB + r) * NN + kk + c * 8);
        }
    };

    const int rowoff = (lane & 7) + ((lane >> 3) & 1) * 8;
    const int koff   = (lane >> 4) * 8;

    float acc[2][8][4];
    #pragma unroll
    for (int i = 0; i < 2; i++)
        #pragma unroll
        for (int j = 0; j < 8; j++)
            #pragma unroll
            for (int k = 0; k < 4; k++) acc[i][j][k] = 0.0f;

    load_stage(0); asm volatile("cp.async.commit_group;");
    load_stage(1); asm volatile("cp.async.commit_group;");

    for (int t = 0; t < NT; t++) {
        asm volatile("cp.async.wait_group 1;");
        __syncthreads();
        if (t + 2 < NT) { load_stage(t + 2); }
        asm volatile("cp.async.commit_group;");

        uint32_t sA = sbase + (t % NSTG) * STG_BYTES;
        uint32_t sB = sA + A_BYTES;
        #pragma unroll
        for (int ks = 0; ks < 4; ks++) {
            const int kbase = ks * 16 + koff;
            uint32_t a[2][4];
            #pragma unroll
            for (int mt = 0; mt < 2; mt++) {
                uint32_t off = ((wm * 32 + mt * 16 + rowoff) * PADK + kbase) * 2;
                ldsm4(a[mt][0], a[mt][1], a[mt][2], a[mt][3], sA + off);
            }
            uint32_t bb[8][2];
            #pragma unroll
            for (int nt2 = 0; nt2 < 4; nt2++) {
                uint32_t off = ((wn * 64 + nt2 * 16 + rowoff) * PADK + kbase) * 2;
                uint32_t d0, d1, d2, d3;
                ldsm4(d0, d1, d2, d3, sB + off);
                bb[nt2 * 2][0] = d0;     bb[nt2 * 2][1] = d2;
                bb[nt2 * 2 + 1][0] = d1; bb[nt2 * 2 + 1][1] = d3;
            }
            #pragma unroll
            for (int mt = 0; mt < 2; mt++)
                #pragma unroll
                for (int nt = 0; nt < 8; nt++)
                    mma16816(acc[mt][nt], a[mt], bb[nt]);
        }
    }
    asm volatile("cp.async.wait_group 0;");

    if (MODE == 0) {
        __half* cg = C + (size_t)b * NN2;
        // direct fp16 store of tile (by,bx)
        #pragma unroll
        for (int mt = 0; mt < 2; mt++) {
            int r = rowA + wm * 32 + mt * 16 + (lane >> 2);
            #pragma unroll
            for (int nt = 0; nt < 8; nt++) {
                int c = rowB + wn * 64 + nt * 8 + (lane & 3) * 2;
                *(__half2*)(cg + (size_t)r * NN + c) =
                    __floats2half2_rn(acc[mt][nt][0], acc[mt][nt][1]);
                *(__half2*)(cg + (size_t)(r + 8) * NN + c) =
                    __floats2half2_rn(acc[mt][nt][2], acc[mt][nt][3]);
            }
        }
        if (by != bx) {
            // stage fp16 tile in smem, write mirrored tile (bx,by)
            __half* tf = (__half*)smem;
            __syncthreads();   // pipeline smem reuse
            #pragma unroll
            for (int mt = 0; mt < 2; mt++) {
                int rl = wm * 32 + mt * 16 + (lane >> 2);
                #pragma unroll
                for (int nt = 0; nt < 8; nt++) {
                    int clc = wn * 64 + nt * 8 + (lane & 3) * 2;
                    *(__half2*)&tf[rl * TFS + clc] =
                        __floats2half2_rn(acc[mt][nt][0], acc[mt][nt][1]);
                    *(__half2*)&tf[(rl + 8) * TFS + clc] =
                        __floats2half2_rn(acc[mt][nt][2], acc[mt][nt][3]);
                }
            }
            __syncthreads();
            const int cc = tid >> 1;
            const int hh = (tid & 1) * 64;
            __half* cp = cg + (size_t)(rowB + cc) * NN + rowA + hh;
            #pragma unroll
            for (int g = 0; g < 8; g++) {
                __align__(16) __half hb[8];
                #pragma unroll
                for (int e = 0; e < 8; e++)
                    hb[e] = tf[(hh + g * 8 + e) * TFS + cc];
                *(uint4*)(cp + g * 8) = *(uint4*)hb;
            }
        }
    } else {
        // fused rowmax over the N axis
        #pragma unroll
        for (int mt = 0; mt < 2; mt++) {
            float m0 = -__int_as_float(0x7f800000), m1 = m0;
            #pragma unroll
            for (int nt = 0; nt < 8; nt++) {
                m0 = fmaxf(m0, fmaxf(acc[mt][nt][0], acc[mt][nt][1]));
                m1 = fmaxf(m1, fmaxf(acc[mt][nt][2], acc[mt][nt][3]));
            }
            m0 = fmaxf(m0, __shfl_xor_sync(0xFFFFFFFFu, m0, 1));
            m0 = fmaxf(m0, __shfl_xor_sync(0xFFFFFFFFu, m0, 2));
            m1 = fmaxf(m1, __shfl_xor_sync(0xFFFFFFFFu, m1, 1));
            m1 = fmaxf(m1, __shfl_xor_sync(0xFFFFFFFFu, m1, 2));
            if ((lane & 3) == 0) {
                int r = rowA + wm * 32 + mt * 16 + (lane >> 2);
                atomicMax(&g_m[b * NN + r], float_ord(m0));
                atomicMax(&g_m[b * NN + r + 8], float_ord(m1));
            }
        }
    }
}

// out[b][n][c] = SCALE * rowmax[b][c] * v[b][n]
__global__ void out_kernel(float* __restrict__ out) {
    size_t idx = (size_t)blockIdx.x * 256 + threadIdx.x;
    int c = (int)(idx & (NN - 1));
    size_t r = idx >> 11;
    int n = (int)(r & (NN - 1));
    int b = (int)(r >> 11);
    out[idx] = SCALE * ord_float(g_m[b * NN + c]) * g_v[b * NN + n];
}

extern "C" void kernel_launch(void* const* d_in, const int* in_sizes, int n_in,
                              void* d_out, int out_size) {
    const float* x  = (const float*)d_in[0];
    const float* Wq = (const float*)d_in[1];
    float* out = (float*)d_out;

    cudaFuncSetAttribute(hgemm<0>, cudaFuncAttributeMaxDynamicSharedMemorySize, SMEM_BYTES);
    cudaFuncSetAttribute(hgemm<1>, cudaFuncAttributeMaxDynamicSharedMemorySize, SMEM_BYTES);

    convert_wq<<<NN2 / 4 / 256, 256>>>(Wq);
    convert_x_mean<<<dim3(NB, NN / 256, NN / 256), 256>>>(x);

    __half *xh, *G, *wq;
    cudaGetSymbolAddress((void**)&xh, g_xh);
    cudaGetSymbolAddress((void**)&G,  g_G);
    cudaGetSymbolAddress((void**)&wq, g_wq);

    // GEMM1: G = x x^T (fp16, upper-tri tiles, mirrored store)
    hgemm<0><<<dim3(NUT, 1, NB), 256, SMEM_BYTES>>>(
        xh, (size_t)NN2, xh, (size_t)NN2, G);

    // GEMM2: attn = Wq * G^T (G symmetric -> rows), fused rowmax
    hgemm<1><<<dim3(NMT, NMT, NB), 256, SMEM_BYTES>>>(
        wq, 0, G, (size_t)NN2, nullptr);

    out_kernel<<<(int)(((size_t)NB * NN2) / 256), 256>>>(out);
}

// round 13
// speedup vs baseline: 1.2494x; 1.2494x over previous
#include <cuda_runtime.h>
#include <cuda_fp16.h>
#include <cstdint>

// B=8, N=C=2048, heads=8 -> scale = 1/16.
#define NB 8
#define NN 2048
#define NN2 (2048*2048)
#define SCALE 0.0625f

// ---------------- scratch ----------------------------------------------------
__device__ __align__(256) __half g_xh[(size_t)NB * NN2];   // x as fp16
__device__ __align__(256) __half g_G[(size_t)NB * NN2];    // G = x x^T fp16 (full, symmetric)
__device__ __align__(256) __half g_wq[NN2];                // Wq as fp16
__device__ float        g_v[NB * NN];                      // column means of x
__device__ unsigned int g_m[NB * NN];                      // rowmax of attn (ordered uint)

__device__ __forceinline__ unsigned int float_ord(float f) {
    unsigned int u = __float_as_uint(f);
    return (u & 0x80000000u) ? ~u : (u | 0x80000000u);
}
__device__ __forceinline__ float ord_float(unsigned int o) {
    unsigned int u = (o & 0x80000000u) ? (o ^ 0x80000000u) : ~o;
    return __uint_as_float(u);
}

// ---- small kernels ----------------------------------------------------------
// Wq -> fp16, plus folded init of g_v / g_m.
__global__ void convert_wq(const float* __restrict__ Wq) {
    size_t g = (size_t)blockIdx.x * 256 + threadIdx.x;
    float4 f = ((const float4*)Wq)[g];
    ((__half2*)g_wq)[g * 2]     = __floats2half2_rn(f.x, f.y);
    ((__half2*)g_wq)[g * 2 + 1] = __floats2half2_rn(f.z, f.w);
    if (g < NB * NN) { g_v[g] = 0.0f; g_m[g] = 0u; }
}

// Fused x -> fp16 conversion + column-mean accumulation.
__global__ void convert_x_mean(const float* __restrict__ x) {
    int b = blockIdx.x;
    int c = blockIdx.y * 256 + threadIdx.x;
    int n0 = blockIdx.z * 256;
    const float* xp = x + ((size_t)b * NN + n0) * NN + c;
    __half* hp = g_xh + ((size_t)b * NN + n0) * NN + c;
    float s = 0.0f;
    #pragma unroll 8
    for (int n = 0; n < 256; n++) {
        float f = xp[(size_t)n * NN];
        hp[(size_t)n * NN] = __float2half_rn(f);
        s += f;
    }
    atomicAdd(&g_v[b * NN + c], s * (1.0f / (float)NN));
}

// ---------------- HMMA GEMM (mma.sync m16n8k16 fp16, fp32 accum) -------------
#define BM 128
#define BN 128
#define BKT 32
#define PADK 40                         // fp16 per smem row; 80B stride
#define A_BYTES (BM * PADK * 2)         // 10240
#define STG_BYTES (2 * A_BYTES)
#define NSTG 4
#define SMEM_BYTES (NSTG * STG_BYTES)   // 81920 (> 128*130*2 = 33280 epi buffer)
#define NT 64                           // 64 k-tiles of 32 = K 2048
#define TFS 130                         // epi transpose buffer row stride (even)

#define NMT 16
#define NUT 136

__device__ __forceinline__ void ldsm4(uint32_t& d0, uint32_t& d1, uint32_t& d2,
                                      uint32_t& d3, uint32_t addr) {
    asm volatile("ldmatrix.sync.aligned.m8n8.x4.shared.b16 {%0,%1,%2,%3}, [%4];"
                 : "=r"(d0), "=r"(d1), "=r"(d2), "=r"(d3) : "r"(addr));
}
__device__ __forceinline__ void mma16816(float* c, const uint32_t* a, const uint32_t* b) {
    asm volatile(
        "mma.sync.aligned.m16n8k16.row.col.f32.f16.f16.f32 "
        "{%0,%1,%2,%3}, {%4,%5,%6,%7}, {%8,%9}, {%0,%1,%2,%3};"
        : "+f"(c[0]), "+f"(c[1]), "+f"(c[2]), "+f"(c[3])
        : "r"(a[0]), "r"(a[1]), "r"(a[2]), "r"(a[3]), "r"(b[0]), "r"(b[1]));
}
__device__ __forceinline__ void cp16(uint32_t dst, const void* src) {
    asm volatile("cp.async.cg.shared.global [%0], [%1], 16;" :: "r"(dst), "l"(src));
}

// MODE 0: symmetric GEMM (G = A A^T, upper tiles, direct + mirrored fp16 store)
// MODE 1: GEMM A*B^T with fused rowmax over N axis into g_m
template<int MODE>
__global__ __launch_bounds__(256, 2) void hgemm(
    const __half* __restrict__ A, size_t aStride,
    const __half* __restrict__ B, size_t bStride,
    __half* __restrict__ C)
{
    extern __shared__ __align__(16) char smem[];
    const int tid  = threadIdx.x;
    const int lane = tid & 31;
    const int w    = tid >> 5;
    const int wm   = w >> 1;
    const int wn   = w & 1;
    const int b    = blockIdx.z;

    int by, bx;
    if (MODE == 0) {                 // decode upper-tri linear index
        int t = blockIdx.x, i = 0;
        while (t >= NMT - i) { t -= NMT - i; i++; }
        by = i; bx = i + t;
    } else {
        by = blockIdx.y; bx = blockIdx.x;
    }
    const int rowA = by * BM;
    const int rowB = bx * BN;

    const __half* Ab = A + (size_t)b * aStride;
    const __half* Bb = B + (size_t)b * bStride;

    const uint32_t sbase = (uint32_t)__cvta_generic_to_shared(smem);

    const int q0 = tid * 2, q1 = tid * 2 + 1;
    const int r0c = q0 >> 2, k0c = q0 & 3;
    const int r1c = q1 >> 2, k1c = q1 & 3;

    auto load_stage = [&](int tile) {
        uint32_t sb = sbase + (tile & (NSTG - 1)) * STG_BYTES;
        const int kk = tile * BKT;
        cp16(sb + r0c * 80 + k0c * 16, Ab + (size_t)(rowA + r0c) * NN + kk + k0c * 8);
        cp16(sb + r1c * 80 + k1c * 16, Ab + (size_t)(rowA + r1c) * NN + kk + k1c * 8);
        cp16(sb + A_BYTES + r0c * 80 + k0c * 16, Bb + (size_t)(rowB + r0c) * NN + kk + k0c * 8);
        cp16(sb + A_BYTES + r1c * 80 + k1c * 16, Bb + (size_t)(rowB + r1c) * NN + kk + k1c * 8);
    };

    const int rowoff = (lane & 7) + ((lane >> 3) & 1) * 8;
    const int koff   = (lane >> 4) * 8;

    float acc[2][8][4];
    #pragma unroll
    for (int i = 0; i < 2; i++)
        #pragma unroll
        for (int j = 0; j < 8; j++)
            #pragma unroll
            for (int k = 0; k < 4; k++) acc[i][j][k] = 0.0f;

    // warp-parity k-step ordering: even warps do ks {0,1}, odd warps {1,0},
    // so one group's MMAs overlap the other group's LDSM convoy.
    const int ksFirst = w & 1;

    uint32_t a[2][4], bb[8][2];
    auto load_frags = [&](uint32_t sA, uint32_t sB, int ks) {
        const int kbase = ks * 16 + koff;
        #pragma unroll
        for (int mt = 0; mt < 2; mt++) {
            uint32_t off = ((wm * 32 + mt * 16 + rowoff) * PADK + kbase) * 2;
            ldsm4(a[mt][0], a[mt][1], a[mt][2], a[mt][3], sA + off);
        }
        #pragma unroll
        for (int nt2 = 0; nt2 < 4; nt2++) {
            uint32_t off = ((wn * 64 + nt2 * 16 + rowoff) * PADK + kbase) * 2;
            uint32_t d0, d1, d2, d3;
            ldsm4(d0, d1, d2, d3, sB + off);
            bb[nt2 * 2][0] = d0;     bb[nt2 * 2][1] = d2;
            bb[nt2 * 2 + 1][0] = d1; bb[nt2 * 2 + 1][1] = d3;
        }
    };
    auto mma_all = [&]() {
        #pragma unroll
        for (int mt = 0; mt < 2; mt++)
            #pragma unroll
            for (int nt = 0; nt < 8; nt++)
                mma16816(acc[mt][nt], a[mt], bb[nt]);
    };

    load_stage(0); asm volatile("cp.async.commit_group;");
    load_stage(1); asm volatile("cp.async.commit_group;");
    load_stage(2); asm volatile("cp.async.commit_group;");

    for (int t = 0; t < NT; t++) {
        asm volatile("cp.async.wait_group 2;");
        __syncthreads();

        uint32_t sA = sbase + (t & (NSTG - 1)) * STG_BYTES;
        uint32_t sB = sA + A_BYTES;

        // first k-step fragments, THEN next-tile cp.async (LSU burst lands in
        // the MMA shadow instead of contending with the LDSM convoy), then MMA.
        load_frags(sA, sB, ksFirst);
        if (t + 3 < NT) load_stage(t + 3);
        asm volatile("cp.async.commit_group;");
        mma_all();

        load_frags(sA, sB, ksFirst ^ 1);
        mma_all();
    }
    asm volatile("cp.async.wait_group 0;");

    if (MODE == 0) {
        __half* cg = C + (size_t)b * NN2;
        // direct fp16 store of tile (by,bx)
        #pragma unroll
        for (int mt = 0; mt < 2; mt++) {
            int r = rowA + wm * 32 + mt * 16 + (lane >> 2);
            #pragma unroll
            for (int nt = 0; nt < 8; nt++) {
                int c = rowB + wn * 64 + nt * 8 + (lane & 3) * 2;
                *(__half2*)(cg + (size_t)r * NN + c) =
                    __floats2half2_rn(acc[mt][nt][0], acc[mt][nt][1]);
                *(__half2*)(cg + (size_t)(r + 8) * NN + c) =
                    __floats2half2_rn(acc[mt][nt][2], acc[mt][nt][3]);
            }
        }
        if (by != bx) {
            // stage fp16 tile in smem, write mirrored tile (bx,by)
            __half* tf = (__half*)smem;
            __syncthreads();   // pipeline smem reuse
            #pragma unroll
            for (int mt = 0; mt < 2; mt++) {
                int rl = wm * 32 + mt * 16 + (lane >> 2);
                #pragma unroll
                for (int nt = 0; nt < 8; nt++) {
                    int clc = wn * 64 + nt * 8 + (lane & 3) * 2;
                    *(__half2*)&tf[rl * TFS + clc] =
                        __floats2half2_rn(acc[mt][nt][0], acc[mt][nt][1]);
                    *(__half2*)&tf[(rl + 8) * TFS + clc] =
                        __floats2half2_rn(acc[mt][nt][2], acc[mt][nt][3]);
                }
            }
            __syncthreads();
            const int cc = tid >> 1;
            const int hh = (tid & 1) * 64;
            __half* cp = cg + (size_t)(rowB + cc) * NN + rowA + hh;
            #pragma unroll
            for (int g = 0; g < 8; g++) {
                __align__(16) __half hb[8];
                #pragma unroll
                for (int e = 0; e < 8; e++)
                    hb[e] = tf[(hh + g * 8 + e) * TFS + cc];
                *(uint4*)(cp + g * 8) = *(uint4*)hb;
            }
        }
    } else {
        // fused rowmax over the N axis
        #pragma unroll
        for (int mt = 0; mt < 2; mt++) {
            float m0 = -__int_as_float(0x7f800000), m1 = m0;
            #pragma unroll
            for (int nt = 0; nt < 8; nt++) {
                m0 = fmaxf(m0, fmaxf(acc[mt][nt][0], acc[mt][nt][1]));
                m1 = fmaxf(m1, fmaxf(acc[mt][nt][2], acc[mt][nt][3]));
            }
            m0 = fmaxf(m0, __shfl_xor_sync(0xFFFFFFFFu, m0, 1));
            m0 = fmaxf(m0, __shfl_xor_sync(0xFFFFFFFFu, m0, 2));
            m1 = fmaxf(m1, __shfl_xor_sync(0xFFFFFFFFu, m1, 1));
            m1 = fmaxf(m1, __shfl_xor_sync(0xFFFFFFFFu, m1, 2));
            if ((lane & 3) == 0) {
                int r = rowA + wm * 32 + mt * 16 + (lane >> 2);
                atomicMax(&g_m[b * NN + r], float_ord(m0));
                atomicMax(&g_m[b * NN + r + 8], float_ord(m1));
            }
        }
    }
}

// out[b][n][c] = SCALE * rowmax[b][c] * v[b][n]
__global__ void out_kernel(float* __restrict__ out) {
    size_t idx = (size_t)blockIdx.x * 256 + threadIdx.x;
    int c = (int)(idx & (NN - 1));
    size_t r = idx >> 11;
    int n = (int)(r & (NN - 1));
    int b = (int)(r >> 11);
    out[idx] = SCALE * ord_float(g_m[b * NN + c]) * g_v[b * NN + n];
}

extern "C" void kernel_launch(void* const* d_in, const int* in_sizes, int n_in,
                              void* d_out, int out_size) {
    const float* x  = (const float*)d_in[0];
    const float* Wq = (const float*)d_in[1];
    float* out = (float*)d_out;

    cudaFuncSetAttribute(hgemm<0>, cudaFuncAttributeMaxDynamicSharedMemorySize, SMEM_BYTES);
    cudaFuncSetAttribute(hgemm<1>, cudaFuncAttributeMaxDynamicSharedMemorySize, SMEM_BYTES);

    convert_wq<<<NN2 / 4 / 256, 256>>>(Wq);
    convert_x_mean<<<dim3(NB, NN / 256, NN / 256), 256>>>(x);

    __half *xh, *G, *wq;
    cudaGetSymbolAddress((void**)&xh, g_xh);
    cudaGetSymbolAddress((void**)&G,  g_G);
    cudaGetSymbolAddress((void**)&wq, g_wq);

    // GEMM1: G = x x^T (fp16, upper-tri tiles, mirrored store)
    hgemm<0><<<dim3(NUT, 1, NB), 256, SMEM_BYTES>>>(
        xh, (size_t)NN2, xh, (size_t)NN2, G);

    // GEMM2: attn = Wq * G^T (G symmetric -> rows), fused rowmax
    hgemm<1><<<dim3(NMT, NMT, NB), 256, SMEM_BYTES>>>(
        wq, 0, G, (size_t)NN2, nullptr);

    out_kernel<<<(int)(((size_t)NB * NN2) / 256), 256>>>(out);
}

// round 14
// speedup vs baseline: 1.3224x; 1.0585x over previous
#include <cuda_runtime.h>
#include <cuda_fp16.h>
#include <cstdint>

// B=8, N=C=2048, heads=8 -> scale = 1/16.
#define NB 8
#define NN 2048
#define NN2 (2048*2048)
#define SCALE 0.0625f

// ---------------- scratch ----------------------------------------------------
__device__ __align__(256) __half g_xh[(size_t)NB * NN2];   // x as fp16
__device__ __align__(256) __half g_G[(size_t)NB * NN2];    // G = x x^T fp16 (full, symmetric)
__device__ __align__(256) __half g_wq[NN2];                // Wq as fp16
__device__ float        g_v[NB * NN];                      // column means of x
__device__ unsigned int g_m[NB * NN];                      // rowmax of attn (ordered uint)

__device__ __forceinline__ unsigned int float_ord(float f) {
    unsigned int u = __float_as_uint(f);
    return (u & 0x80000000u) ? ~u : (u | 0x80000000u);
}
__device__ __forceinline__ float ord_float(unsigned int o) {
    unsigned int u = (o & 0x80000000u) ? (o ^ 0x80000000u) : ~o;
    return __uint_as_float(u);
}

// ---- small kernels ----------------------------------------------------------
// Wq -> fp16, plus folded init of g_v / g_m.
__global__ void convert_wq(const float* __restrict__ Wq) {
    size_t g = (size_t)blockIdx.x * 256 + threadIdx.x;
    float4 f = ((const float4*)Wq)[g];
    ((__half2*)g_wq)[g * 2]     = __floats2half2_rn(f.x, f.y);
    ((__half2*)g_wq)[g * 2 + 1] = __floats2half2_rn(f.z, f.w);
    if (g < NB * NN) { g_v[g] = 0.0f; g_m[g] = 0u; }
}

// Fused x -> fp16 conversion + column-mean accumulation.
__global__ void convert_x_mean(const float* __restrict__ x) {
    int b = blockIdx.x;
    int c = blockIdx.y * 256 + threadIdx.x;
    int n0 = blockIdx.z * 256;
    const float* xp = x + ((size_t)b * NN + n0) * NN + c;
    __half* hp = g_xh + ((size_t)b * NN + n0) * NN + c;
    float s = 0.0f;
    #pragma unroll 8
    for (int n = 0; n < 256; n++) {
        float f = xp[(size_t)n * NN];
        hp[(size_t)n * NN] = __float2half_rn(f);
        s += f;
    }
    atomicAdd(&g_v[b * NN + c], s * (1.0f / (float)NN));
}

// ---------------- HMMA GEMM (mma.sync m16n8k16 fp16, fp32 accum) -------------
#define BM 128
#define BN 128
#define BKT 32
#define PADK 40                         // fp16 per smem row; 80B stride
#define A_BYTES (BM * PADK * 2)         // 10240
#define STG_BYTES (2 * A_BYTES)
#define NSTG 4
#define SMEM_BYTES (NSTG * STG_BYTES)   // 81920 (> 128*130*2 = 33280 epi buffer)
#define NT 64                           // 64 k-tiles of 32 = K 2048
#define TFS 130                         // epi transpose buffer row stride (even)

#define NMT 16
#define NUT 136

__device__ __forceinline__ void ldsm4(uint32_t& d0, uint32_t& d1, uint32_t& d2,
                                      uint32_t& d3, uint32_t addr) {
    asm volatile("ldmatrix.sync.aligned.m8n8.x4.shared.b16 {%0,%1,%2,%3}, [%4];"
                 : "=r"(d0), "=r"(d1), "=r"(d2), "=r"(d3) : "r"(addr));
}
__device__ __forceinline__ void mma16816(float* c, const uint32_t* a, const uint32_t* b) {
    asm volatile(
        "mma.sync.aligned.m16n8k16.row.col.f32.f16.f16.f32 "
        "{%0,%1,%2,%3}, {%4,%5,%6,%7}, {%8,%9}, {%0,%1,%2,%3};"
        : "+f"(c[0]), "+f"(c[1]), "+f"(c[2]), "+f"(c[3])
        : "r"(a[0]), "r"(a[1]), "r"(a[2]), "r"(a[3]), "r"(b[0]), "r"(b[1]));
}
__device__ __forceinline__ void cp16(uint32_t dst, const void* src) {
    asm volatile("cp.async.cg.shared.global [%0], [%1], 16;" :: "r"(dst), "l"(src));
}

// MODE 0: symmetric GEMM (G = A A^T, upper tiles, direct + mirrored fp16 store)
// MODE 1: GEMM A*B^T with fused rowmax over N axis into g_m
template<int MODE>
__global__ __launch_bounds__(256, 2) void hgemm(
    const __half* __restrict__ A, size_t aStride,
    const __half* __restrict__ B, size_t bStride,
    __half* __restrict__ C)
{
    extern __shared__ __align__(16) char smem[];
    const int tid  = threadIdx.x;
    const int lane = tid & 31;
    const int w    = tid >> 5;
    const int wm   = w >> 1;
    const int wn   = w & 1;
    const int b    = blockIdx.z;

    int by, bx;
    if (MODE == 0) {                 // decode upper-tri linear index
        int t = blockIdx.x, i = 0;
        while (t >= NMT - i) { t -= NMT - i; i++; }
        by = i; bx = i + t;
    } else {
        by = blockIdx.y; bx = blockIdx.x;
    }
    const int rowA = by * BM;
    const int rowB = bx * BN;

    const __half* Ab = A + (size_t)b * aStride;
    const __half* Bb = B + (size_t)b * bStride;

    const uint32_t sbase = (uint32_t)__cvta_generic_to_shared(smem);

    const int q0 = tid * 2, q1 = tid * 2 + 1;
    const int r0c = q0 >> 2, k0c = q0 & 3;
    const int r1c = q1 >> 2, k1c = q1 & 3;

    auto load_stage = [&](int tile) {
        uint32_t sb = sbase + (tile & (NSTG - 1)) * STG_BYTES;
        const int kk = tile * BKT;
        cp16(sb + r0c * 80 + k0c * 16, Ab + (size_t)(rowA + r0c) * NN + kk + k0c * 8);
        cp16(sb + r1c * 80 + k1c * 16, Ab + (size_t)(rowA + r1c) * NN + kk + k1c * 8);
        cp16(sb + A_BYTES + r0c * 80 + k0c * 16, Bb + (size_t)(rowB + r0c) * NN + kk + k0c * 8);
        cp16(sb + A_BYTES + r1c * 80 + k1c * 16, Bb + (size_t)(rowB + r1c) * NN + kk + k1c * 8);
    };

    const int rowoff = (lane & 7) + ((lane >> 3) & 1) * 8;
    const int koff   = (lane >> 4) * 8;

    float acc[2][8][4];
    #pragma unroll
    for (int i = 0; i < 2; i++)
        #pragma unroll
        for (int j = 0; j < 8; j++)
            #pragma unroll
            for (int k = 0; k < 4; k++) acc[i][j][k] = 0.0f;

    // warp-parity k-step ordering (R13) + two register fragment buffers (R14):
    // every LDSM convoy is issued under the previous buffer's MMA block.
    const int ksFirst = w & 1;

    uint32_t a[2][2][4], bb[2][8][2];
    auto load_frags = [&](int buf, uint32_t sA, uint32_t sB, int ks) {
        const int kbase = ks * 16 + koff;
        #pragma unroll
        for (int mt = 0; mt < 2; mt++) {
            uint32_t off = ((wm * 32 + mt * 16 + rowoff) * PADK + kbase) * 2;
            ldsm4(a[buf][mt][0], a[buf][mt][1], a[buf][mt][2], a[buf][mt][3], sA + off);
        }
        #pragma unroll
        for (int nt2 = 0; nt2 < 4; nt2++) {
            uint32_t off = ((wn * 64 + nt2 * 16 + rowoff) * PADK + kbase) * 2;
            uint32_t d0, d1, d2, d3;
            ldsm4(d0, d1, d2, d3, sB + off);
            bb[buf][nt2 * 2][0] = d0;     bb[buf][nt2 * 2][1] = d2;
            bb[buf][nt2 * 2 + 1][0] = d1; bb[buf][nt2 * 2 + 1][1] = d3;
        }
    };
    auto mma_all = [&](int buf) {
        #pragma unroll
        for (int mt = 0; mt < 2; mt++)
            #pragma unroll
            for (int nt = 0; nt < 8; nt++)
                mma16816(acc[mt][nt], a[buf][mt], bb[buf][nt]);
    };

    load_stage(0); asm volatile("cp.async.commit_group;");
    load_stage(1); asm volatile("cp.async.commit_group;");
    load_stage(2); asm volatile("cp.async.commit_group;");

    // prologue: stage 0 ready, preload buf0 frags (ksFirst)
    asm volatile("cp.async.wait_group 2;");
    __syncthreads();
    {
        uint32_t sA0 = sbase;
        load_frags(0, sA0, sA0 + A_BYTES, ksFirst);
    }

    for (int t = 0; t < NT; t++) {
        uint32_t sA = sbase + (t & (NSTG - 1)) * STG_BYTES;
        uint32_t sB = sA + A_BYTES;

        // second k-step frags into buf1 (covered below by mma(buf0))
        load_frags(1, sA, sB, ksFirst ^ 1);
        if (t + 3 < NT) load_stage(t + 3);
        asm volatile("cp.async.commit_group;");
        mma_all(0);                       // covers buf1 LDSM + cp.async burst

        asm volatile("cp.async.wait_group 2;");
        __syncthreads();                  // stage t+1 ready; stage t reads done

        if (t + 1 < NT) {
            uint32_t nA = sbase + ((t + 1) & (NSTG - 1)) * STG_BYTES;
            load_frags(0, nA, nA + A_BYTES, ksFirst);   // covered by mma(buf1)
        }
        mma_all(1);
    }
    asm volatile("cp.async.wait_group 0;");

    if (MODE == 0) {
        __half* cg = C + (size_t)b * NN2;
        // direct fp16 store of tile (by,bx)
        #pragma unroll
        for (int mt = 0; mt < 2; mt++) {
            int r = rowA + wm * 32 + mt * 16 + (lane >> 2);
            #pragma unroll
            for (int nt = 0; nt < 8; nt++) {
                int c = rowB + wn * 64 + nt * 8 + (lane & 3) * 2;
                *(__half2*)(cg + (size_t)r * NN + c) =
                    __floats2half2_rn(acc[mt][nt][0], acc[mt][nt][1]);
                *(__half2*)(cg + (size_t)(r + 8) * NN + c) =
                    __floats2half2_rn(acc[mt][nt][2], acc[mt][nt][3]);
            }
        }
        if (by != bx) {
            // stage fp16 tile in smem, write mirrored tile (bx,by)
            __half* tf = (__half*)smem;
            __syncthreads();   // pipeline smem reuse
            #pragma unroll
            for (int mt = 0; mt < 2; mt++) {
                int rl = wm * 32 + mt * 16 + (lane >> 2);
                #pragma unroll
                for (int nt = 0; nt < 8; nt++) {
                    int clc = wn * 64 + nt * 8 + (lane & 3) * 2;
                    *(__half2*)&tf[rl * TFS + clc] =
                        __floats2half2_rn(acc[mt][nt][0], acc[mt][nt][1]);
                    *(__half2*)&tf[(rl + 8) * TFS + clc] =
                        __floats2half2_rn(acc[mt][nt][2], acc[mt][nt][3]);
                }
            }
            __syncthreads();
            const int cc = tid >> 1;
            const int hh = (tid & 1) * 64;
            __half* cp = cg + (size_t)(rowB + cc) * NN + rowA + hh;
            #pragma unroll
            for (int g = 0; g < 8; g++) {
                __align__(16) __half hb[8];
                #pragma unroll
                for (int e = 0; e < 8; e++)
                    hb[e] = tf[(hh + g * 8 + e) * TFS + cc];
                *(uint4*)(cp + g * 8) = *(uint4*)hb;
            }
        }
    } else {
        // fused rowmax over the N axis
        #pragma unroll
        for (int mt = 0; mt < 2; mt++) {
            float m0 = -__int_as_float(0x7f800000), m1 = m0;
            #pragma unroll
            for (int nt = 0; nt < 8; nt++) {
                m0 = fmaxf(m0, fmaxf(acc[mt][nt][0], acc[mt][nt][1]));
                m1 = fmaxf(m1, fmaxf(acc[mt][nt][2], acc[mt][nt][3]));
            }
            m0 = fmaxf(m0, __shfl_xor_sync(0xFFFFFFFFu, m0, 1));
            m0 = fmaxf(m0, __shfl_xor_sync(0xFFFFFFFFu, m0, 2));
            m1 = fmaxf(m1, __shfl_xor_sync(0xFFFFFFFFu, m1, 1));
            m1 = fmaxf(m1, __shfl_xor_sync(0xFFFFFFFFu, m1, 2));
            if ((lane & 3) == 0) {
                int r = rowA + wm * 32 + mt * 16 + (lane >> 2);
                atomicMax(&g_m[b * NN + r], float_ord(m0));
                atomicMax(&g_m[b * NN + r + 8], float_ord(m1));
            }
        }
    }
}

// out[b][n][c] = SCALE * rowmax[b][c] * v[b][n]
__global__ void out_kernel(float* __restrict__ out) {
    size_t idx = (size_t)blockIdx.x * 256 + threadIdx.x;
    int c = (int)(idx & (NN - 1));
    size_t r = idx >> 11;
    int n = (int)(r & (NN - 1));
    int b = (int)(r >> 11);
    out[idx] = SCALE * ord_float(g_m[b * NN + c]) * g_v[b * NN + n];
}

extern "C" void kernel_launch(void* const* d_in, const int* in_sizes, int n_in,
                              void* d_out, int out_size) {
    const float* x  = (const float*)d_in[0];
    const float* Wq = (const float*)d_in[1];
    float* out = (float*)d_out;

    cudaFuncSetAttribute(hgemm<0>, cudaFuncAttributeMaxDynamicSharedMemorySize, SMEM_BYTES);
    cudaFuncSetAttribute(hgemm<1>, cudaFuncAttributeMaxDynamicSharedMemorySize, SMEM_BYTES);

    convert_wq<<<NN2 / 4 / 256, 256>>>(Wq);
    convert_x_mean<<<dim3(NB, NN / 256, NN / 256), 256>>>(x);

    __half *xh, *G, *wq;
    cudaGetSymbolAddress((void**)&xh, g_xh);
    cudaGetSymbolAddress((void**)&G,  g_G);
    cudaGetSymbolAddress((void**)&wq, g_wq);

    // GEMM1: G = x x^T (fp16, upper-tri tiles, mirrored store)
    hgemm<0><<<dim3(NUT, 1, NB), 256, SMEM_BYTES>>>(
        xh, (size_t)NN2, xh, (size_t)NN2, G);

    // GEMM2: attn = Wq * G^T (G symmetric -> rows), fused rowmax
    hgemm<1><<<dim3(NMT, NMT, NB), 256, SMEM_BYTES>>>(
        wq, 0, G, (size_t)NN2, nullptr);

    out_kernel<<<(int)(((size_t)NB * NN2) / 256), 256>>>(out);
}